// round 14
// baseline (speedup 1.0000x reference)
#include <cuda_runtime.h>

#define NP 262144          // 2048*128 points
#define GD3 884736         // 96^3

typedef unsigned long long u64;

__device__ __forceinline__ u64 pk2(float lo, float hi) {
    u64 r; asm("mov.b64 %0, {%1,%2};" : "=l"(r) : "f"(lo), "f"(hi)); return r;
}
__device__ __forceinline__ void upk2(u64 v, float& lo, float& hi) {
    asm("mov.b64 {%0,%1}, %2;" : "=f"(lo), "=f"(hi) : "l"(v));
}
__device__ __forceinline__ u64 ffma2(u64 a, u64 b, u64 c) {
    u64 d; asm("fma.rn.f32x2 %0, %1, %2, %3;" : "=l"(d) : "l"(a), "l"(b), "l"(c)); return d;
}

// ---------------- scratch (static device globals; allocation-free) ----------------
__device__ float g_feats[NP * 32];          // [pt][32] point-major
__device__ float g_dfp[NP * 96];            // [pt][3][32]
__device__ float g_H1[(size_t)NP * 256];    // k-major per block: [block][256][64]
__device__ float g_H2[(size_t)NP * 256];    // k-major per block: [block][256][64]
__device__ float g_geo[NP * 15];            // [pt][15]
__device__ float g_W1T[256 * 256];          // [i][j] = W1[j][i]
__device__ float g_W0T[256 * 35];           // [j][i] = W0[i][j]

// ---------------- weight transpose ----------------
__global__ void k_transpose(const float* __restrict__ W0, const float* __restrict__ W1) {
    int total = 256 * 256 + 256 * 35;
    for (int g = blockIdx.x * blockDim.x + threadIdx.x; g < total; g += gridDim.x * blockDim.x) {
        if (g < 65536) {
            int j = g >> 8, i = g & 255;
            g_W1T[j * 256 + i] = W1[i * 256 + j];
        } else {
            int t = g - 65536;
            int j = t / 35, i = t - j * 35;
            g_W0T[t] = W0[i * 256 + j];
        }
    }
}

// ---------------- trilinear sampling: feats + d feat/d p ----------------
__global__ void k_sample(const float* __restrict__ pts,
                         const float* __restrict__ vol0,
                         const float* __restrict__ vol1) {
    extern __shared__ float sm[];
    float* sFeat = sm;            // 64*33 (padded)
    float* sDfp  = sm + 2112;     // 64*97 (padded)
    int tid = threadIdx.x;
    int p = blockIdx.x * 64 + tid;

    float px = pts[p * 3 + 0], py = pts[p * 3 + 1], pz = pts[p * 3 + 2];
    float x = px * 95.f, y = py * 95.f, z = pz * 95.f;
    int x0 = (int)floorf(x); x0 = min(max(x0, 0), 94);
    int y0 = (int)floorf(y); y0 = min(max(y0, 0), 94);
    int z0 = (int)floorf(z); z0 = min(max(z0, 0), 94);
    float xd = x - (float)x0, yd = y - (float)y0, zd = z - (float)z0;
    float wx0 = 1.f - xd, wx1 = xd;
    float wy0 = 1.f - yd, wy1 = yd;
    float wz0 = 1.f - zd, wz1 = zd;

    int base = (z0 * 96 + y0) * 96 + x0;
    const float* vols[2] = { vol0, vol1 };

    #pragma unroll
    for (int v = 0; v < 2; v++) {
        const float* vb = vols[v] + base;
        #pragma unroll 4
        for (int c = 0; c < 16; c++) {
            const float* q = vb + c * GD3;
            float v000 = __ldg(q);        float v001 = __ldg(q + 1);
            float v010 = __ldg(q + 96);   float v011 = __ldg(q + 97);
            float v100 = __ldg(q + 9216); float v101 = __ldg(q + 9217);
            float v110 = __ldg(q + 9312); float v111 = __ldg(q + 9313);
            float feat = wz0 * (wy0 * (v000 * wx0 + v001 * wx1) + wy1 * (v010 * wx0 + v011 * wx1))
                       + wz1 * (wy0 * (v100 * wx0 + v101 * wx1) + wy1 * (v110 * wx0 + v111 * wx1));
            float dfx = 95.f * (wz0 * (wy0 * (v001 - v000) + wy1 * (v011 - v010))
                              + wz1 * (wy0 * (v101 - v100) + wy1 * (v111 - v110)));
            float dfy = 95.f * (wz0 * (wx0 * (v010 - v000) + wx1 * (v011 - v001))
                              + wz1 * (wx0 * (v110 - v100) + wx1 * (v111 - v101)));
            float dfz = 95.f * (wy0 * (wx0 * (v100 - v000) + wx1 * (v101 - v001))
                              + wy1 * (wx0 * (v110 - v010) + wx1 * (v111 - v011)));
            int fi = (c >> 3) * 16 + v * 8 + (c & 7);
            sFeat[tid * 33 + fi] = feat;
            sDfp[tid * 97 + fi]      = dfx;
            sDfp[tid * 97 + 32 + fi] = dfy;
            sDfp[tid * 97 + 64 + fi] = dfz;
        }
    }
    __syncthreads();
    int fb = blockIdx.x * 64 * 32;
    for (int t = tid; t < 2048; t += 64)
        g_feats[fb + t] = sFeat[(t >> 5) * 33 + (t & 31)];
    int db = blockIdx.x * 64 * 96;
    for (int t = tid; t < 6144; t += 64) {
        int pp = t / 96, q = t - pp * 96;
        g_dfp[db + t] = sDfp[pp * 97 + q];
    }
}

// ---------------- k-major 64pt x 256col GEMM ----------------
// Activations k-major: sAT[k][64]. Output k-major: sOutT[col][64].
// Warp = (pgroup 0..3) x (cgroup 0..1): 16 pts x 128 cols.
// Lane: pr=lane>>3 (4 pts), cr=lane&7 (cols jw + 32q + cr*4, q=0..3).
// Per k per lane: 1 broadcast LDS.128 (4 pts) + 4 coalesced LDS.128 (weights)
// + 32 ffma2. gOutT/gMaskT: per-block k-major [256][64] global.
__device__ __forceinline__ void gemmT(
    const float* sAT, const float* __restrict__ gW, int KD, int CH,
    const float* __restrict__ gBias, float* sOutT, float* sW,
    bool do_relu, float* gOutT, const float* gMaskT)
{
    int tid = threadIdx.x;
    int warp = tid >> 5, lane = tid & 31;
    int pr = lane >> 3, cr = lane & 7;
    int p0 = (warp >> 1) * 16 + pr * 4;     // 4 points for this lane
    int jw = (warp & 1) * 128 + cr * 4;     // col groups at jw + 32q

    u64 acc[4][2][4];                        // [q][colpair][pt]
    #pragma unroll
    for (int q = 0; q < 4; q++)
        #pragma unroll
        for (int par = 0; par < 2; par++) {
            u64 b = gBias ? *(const u64*)(gBias + jw + 32 * q + 2 * par) : 0ull;
            #pragma unroll
            for (int pp = 0; pp < 4; pp++) acc[q][par][pp] = b;
        }

    for (int k0 = 0; k0 < KD; k0 += CH) {
        int kc = KD - k0; if (kc > CH) kc = CH;
        __syncthreads();
        for (int t = tid; t < kc * 64; t += 256) {
            int r = t >> 6, c = t & 63;
            ((float4*)sW)[r * 64 + c] = ((const float4*)(gW + (size_t)(k0 + r) * 256))[c];
        }
        __syncthreads();
        for (int k = 0; k < kc; k++) {
            float4 av = *(const float4*)(sAT + (k0 + k) * 64 + p0);
            u64 a[4] = { pk2(av.x, av.x), pk2(av.y, av.y),
                         pk2(av.z, av.z), pk2(av.w, av.w) };
            const float* wr = sW + k * 256 + jw;
            #pragma unroll
            for (int q = 0; q < 4; q++) {
                float4 wv = *(const float4*)(wr + 32 * q);
                u64 w0 = pk2(wv.x, wv.y), w1 = pk2(wv.z, wv.w);
                #pragma unroll
                for (int pp = 0; pp < 4; pp++) {
                    acc[q][0][pp] = ffma2(a[pp], w0, acc[q][0][pp]);
                    acc[q][1][pp] = ffma2(a[pp], w1, acc[q][1][pp]);
                }
            }
        }
    }
    __syncthreads();   // allow sOutT == sAT
    #pragma unroll
    for (int q = 0; q < 4; q++) {
        #pragma unroll
        for (int par = 0; par < 2; par++) {
            int c0 = jw + 32 * q + 2 * par;
            float lo[4], hi[4];
            #pragma unroll
            for (int pp = 0; pp < 4; pp++) upk2(acc[q][par][pp], lo[pp], hi[pp]);
            if (do_relu) {
                #pragma unroll
                for (int pp = 0; pp < 4; pp++) {
                    lo[pp] = fmaxf(lo[pp], 0.f);
                    hi[pp] = fmaxf(hi[pp], 0.f);
                }
            }
            if (gMaskT) {
                float4 m0 = *(const float4*)(gMaskT + (size_t)c0 * 64 + p0);
                float4 m1 = *(const float4*)(gMaskT + (size_t)(c0 + 1) * 64 + p0);
                lo[0] = (m0.x > 0.f) ? lo[0] : 0.f;  lo[1] = (m0.y > 0.f) ? lo[1] : 0.f;
                lo[2] = (m0.z > 0.f) ? lo[2] : 0.f;  lo[3] = (m0.w > 0.f) ? lo[3] : 0.f;
                hi[0] = (m1.x > 0.f) ? hi[0] : 0.f;  hi[1] = (m1.y > 0.f) ? hi[1] : 0.f;
                hi[2] = (m1.z > 0.f) ? hi[2] : 0.f;  hi[3] = (m1.w > 0.f) ? hi[3] : 0.f;
            }
            float4 e = make_float4(lo[0], lo[1], lo[2], lo[3]);
            float4 o = make_float4(hi[0], hi[1], hi[2], hi[3]);
            *(float4*)(sOutT + c0 * 64 + p0)       = e;
            *(float4*)(sOutT + (c0 + 1) * 64 + p0) = o;
            if (gOutT) {
                *(float4*)(gOutT + (size_t)c0 * 64 + p0)       = e;
                *(float4*)(gOutT + (size_t)(c0 + 1) * 64 + p0) = o;
            }
        }
    }
    __syncthreads();
}

// ---------------- forward MLP ----------------
__global__ __launch_bounds__(256, 2) void k_forward(
    const float* __restrict__ pts,
    const float* __restrict__ W0, const float* __restrict__ b0,
    const float* __restrict__ W1, const float* __restrict__ b1,
    const float* __restrict__ W2, const float* __restrict__ b2,
    float* __restrict__ out)
{
    extern __shared__ float sm[];
    float* sW   = sm;            // 8192 (32-k weight chunks / W2)
    float* sH1T = sm + 8192;     // 16384: k-major [256][64] (H1 then H2)
    float* sXT  = sm + 24576;    // 2304: [36][64]
    int tid = threadIdx.x;
    int pb = blockIdx.x * 64;
    size_t gb = (size_t)blockIdx.x * 16384;

    for (int t = tid; t < 192; t += 256) { int p = t / 3, a = t - p * 3; sXT[a * 64 + p] = pts[(pb + p) * 3 + a]; }
    for (int t = tid; t < 2048; t += 256) { int p = t >> 5, c = t & 31; sXT[(3 + c) * 64 + p] = g_feats[pb * 32 + t]; }
    __syncthreads();

    gemmT(sXT, W0, 35, 32, b0, sH1T, sW, true, g_H1 + gb, nullptr);
    gemmT(sH1T, W1, 256, 32, b1, sH1T, sW, true, g_H2 + gb, nullptr);   // H2 in place

    // layer 3: 256 -> 16 head; W2 staged in sW, H2 read k-major
    for (int t = tid; t < 1024; t += 256) ((float4*)sW)[t] = ((const float4*)W2)[t];
    __syncthreads();
    int jc = tid & 15, pg = tid >> 4;
    float bb = b2[jc];
    float a4[4] = { bb, bb, bb, bb };
    for (int k = 0; k < 256; k++) {
        float w = sW[k * 16 + jc];
        #pragma unroll
        for (int i = 0; i < 4; i++)
            a4[i] = fmaf(sH1T[k * 64 + pg * 4 + i], w, a4[i]);
    }
    #pragma unroll
    for (int i = 0; i < 4; i++) {
        int pt = pb + pg * 4 + i;
        if (jc == 0) out[(size_t)NP * 4 + pt] = a4[i];
        else         g_geo[pt * 15 + jc - 1] = a4[i];
    }
}

// ---------------- backward: gradients of sdf wrt points ----------------
__global__ __launch_bounds__(256, 2) void k_backward(
    const float* __restrict__ W2, float* __restrict__ out)
{
    extern __shared__ float sm[];
    float* sW  = sm;             // 8192 (W1T chunks / W0T half-chunks)
    float* sGT = sm + 8192;      // 16384: k-major [256][64] (G2 then G1)
    float* sGx = sm + 24576;     // 2240
    float* sB  = sm + 26816;     // 256
    int tid = threadIdx.x;
    int pb = blockIdx.x * 64;
    size_t gb = (size_t)blockIdx.x * 16384;

    sB[tid] = W2[tid * 16];      // W2 column 0
    __syncthreads();

    // G2 = relu'(H2) * W2col0 -- H2 k-major so each float4 shares one k
    const float4* h2 = (const float4*)(g_H2 + gb);
    for (int t = tid; t < 4096; t += 256) {
        float4 h = h2[t];
        float w = sB[t >> 4];            // k = t/16
        float4 g;
        g.x = h.x > 0.f ? w : 0.f;
        g.y = h.y > 0.f ? w : 0.f;
        g.z = h.z > 0.f ? w : 0.f;
        g.w = h.w > 0.f ? w : 0.f;
        ((float4*)sGT)[t] = g;
    }
    // G1 = (G2 @ W1^T) * (H1 > 0), in place
    gemmT(sGT, g_W1T, 256, 32, nullptr, sGT, sW, false, nullptr, g_H1 + gb);

    // Gx = G1 @ W0^T (N=35), W0T staged in 2 chunks of 128 k-rows
    #pragma unroll
    for (int ch = 0; ch < 2; ch++) {
        __syncthreads();
        for (int t = tid; t < 4480; t += 256) sW[t] = g_W0T[ch * 4480 + t];
        __syncthreads();
        for (int o = tid; o < 2240; o += 256) {
            int p = o / 35, i = o - p * 35;
            float a = ch ? sGx[o] : 0.f;
            const float* gk = sGT + ch * 128 * 64 + p;
            const float* wk = sW + i;
            for (int k = 0; k < 128; k++)
                a = fmaf(gk[k * 64], wk[k * 35], a);
            sGx[o] = a;
        }
    }
    __syncthreads();
    if (tid < 64) {
        int p = tid, pt = pb + p;
        const float* dfp = g_dfp + (size_t)pt * 96;
        float gx = sGx[p * 35], gy = sGx[p * 35 + 1], gz = sGx[p * 35 + 2];
        #pragma unroll
        for (int c = 0; c < 32; c++) {
            float q = sGx[p * 35 + 3 + c];
            gx = fmaf(q, __ldg(dfp + c),      gx);
            gy = fmaf(q, __ldg(dfp + 32 + c), gy);
            gz = fmaf(q, __ldg(dfp + 64 + c), gz);
        }
        out[(size_t)NP * 5 + pt * 3 + 0] = gx;
        out[(size_t)NP * 5 + pt * 3 + 1] = gy;
        out[(size_t)NP * 5 + pt * 3 + 2] = gz;
        float n = sqrtf(gx * gx + gy * gy + gz * gz);
        float inv = 1.f / fmaxf(n, 1e-12f);
        out[(size_t)NP * 8 + pt * 3 + 0] = gx * inv;
        out[(size_t)NP * 8 + pt * 3 + 1] = gy * inv;
        out[(size_t)NP * 8 + pt * 3 + 2] = gz * inv;
    }
}

// ---------------- RGB head + elementwise outputs ----------------
__global__ __launch_bounds__(256, 2) void k_rgb(
    const float* __restrict__ pts, const float* __restrict__ dirs,
    const float* __restrict__ deltas,
    const float* __restrict__ Wr0, const float* __restrict__ br0,
    const float* __restrict__ Wr1, const float* __restrict__ br1,
    const float* __restrict__ beta, const float* __restrict__ variance,
    float* __restrict__ out)
{
    extern __shared__ float sm[];
    float* sW   = sm;            // 4096 (16-k weight chunks / Wr1)
    float* sHrT = sm + 4096;     // 16384: k-major [256][64]
    float* sXT  = sm + 20480;    // 3584: [56][64]
    int tid = threadIdx.x;
    int pb = blockIdx.x * 64;

    for (int t = tid; t < 192; t += 256) {
        int p = t / 3, a = t - p * 3;
        sXT[a * 64 + p]        = pts[(pb + p) * 3 + a];
        sXT[(3 + a) * 64 + p]  = out[(size_t)NP * 5 + (pb + p) * 3 + a];  // gradients
        sXT[(53 + a) * 64 + p] = dirs[(pb + p) * 3 + a];
    }
    for (int t = tid; t < 2048; t += 256) { int p = t >> 5, c = t & 31; sXT[(6 + c) * 64 + p] = g_feats[pb * 32 + t]; }
    for (int t = tid; t < 960; t += 256) { int p = t / 15, j = t - p * 15; sXT[(38 + j) * 64 + p] = g_geo[pb * 15 + t]; }
    __syncthreads();

    gemmT(sXT, Wr0, 56, 16, br0, sHrT, sW, true, nullptr, nullptr);

    for (int t = tid; t < 768; t += 256) sW[t] = Wr1[t];
    __syncthreads();
    for (int o = tid; o < 192; o += 256) {
        int p = o / 3, c = o - p * 3;
        float a = br1[c];
        for (int k = 0; k < 256; k++)
            a = fmaf(sHrT[k * 64 + p], sW[k * 3 + c], a);
        out[(size_t)(pb + p) * 3 + c] = 1.f / (1.f + expf(-a));
    }

    if (tid < 64) {
        int pt = pb + tid;
        float sdf = out[(size_t)NP * 4 + pt];
        float d   = deltas[pt];
        float gx = out[(size_t)NP * 5 + pt * 3],     gy = out[(size_t)NP * 5 + pt * 3 + 1],
              gz = out[(size_t)NP * 5 + pt * 3 + 2];
        float dx = dirs[pt * 3], dy = dirs[pt * 3 + 1], dz = dirs[pt * 3 + 2];
        float be = fabsf(beta[0]) + 1e-4f;
        float sg = (sdf > 0.f) ? 1.f : ((sdf < 0.f) ? -1.f : 0.f);
        float density = (0.5f + 0.5f * sg * expm1f(-fabsf(sdf) / be)) / be;
        float iv = expf(variance[0] * 10.f);
        iv = fminf(fmaxf(iv, 1e-6f), 1e6f);
        float tc = dx * gx + dy * gy + dz * gz;
        float ic = -fmaxf(-tc, 0.f);                 // COS_ANNEAL = 1
        float en = sdf + ic * d * 0.5f;
        float ep = sdf - ic * d * 0.5f;
        float pc = 1.f / (1.f + expf(-ep * iv));
        float nc = 1.f / (1.f + expf(-en * iv));
        float al = (pc - nc + 1e-5f) / (pc + 1e-5f);
        al = fminf(fmaxf(al, 0.f), 1.f);
        out[(size_t)NP * 3 + pt]  = density;
        out[(size_t)NP * 11 + pt] = al;
    }
}

// ---------------- launch ----------------
extern "C" void kernel_launch(void* const* d_in, const int* in_sizes, int n_in,
                              void* d_out, int out_size) {
    const float* points     = (const float*)d_in[0];
    const float* directions = (const float*)d_in[1];
    const float* deltas     = (const float*)d_in[2];
    const float* vol0       = (const float*)d_in[3];
    const float* vol1       = (const float*)d_in[4];
    const float* W0  = (const float*)d_in[5];
    const float* b0  = (const float*)d_in[6];
    const float* W1  = (const float*)d_in[7];
    const float* b1  = (const float*)d_in[8];
    const float* W2  = (const float*)d_in[9];
    const float* b2  = (const float*)d_in[10];
    const float* Wr0 = (const float*)d_in[11];
    const float* br0 = (const float*)d_in[12];
    const float* Wr1 = (const float*)d_in[13];
    const float* br1 = (const float*)d_in[14];
    const float* beta     = (const float*)d_in[15];
    const float* variance = (const float*)d_in[16];
    float* out = (float*)d_out;

    cudaFuncSetAttribute(k_forward,  cudaFuncAttributeMaxDynamicSharedMemorySize, 26880 * 4);
    cudaFuncSetAttribute(k_backward, cudaFuncAttributeMaxDynamicSharedMemorySize, 27072 * 4);
    cudaFuncSetAttribute(k_rgb,      cudaFuncAttributeMaxDynamicSharedMemorySize, 24064 * 4);

    k_transpose<<<128, 256>>>(W0, W1);
    k_sample<<<NP / 64, 64, 8320 * 4>>>(points, vol0, vol1);
    k_forward<<<NP / 64, 256, 26880 * 4>>>(points, W0, b0, W1, b1, W2, b2, out);
    k_backward<<<NP / 64, 256, 27072 * 4>>>(W2, out);
    k_rgb<<<NP / 64, 256, 24064 * 4>>>(points, directions, deltas,
                                       Wr0, br0, Wr1, br1, beta, variance, out);
}

// round 17
// speedup vs baseline: 1.0378x; 1.0378x over previous
#include <cuda_runtime.h>

#define NP 262144          // 2048*128 points
#define GD3 884736         // 96^3

typedef unsigned long long u64;

__device__ __forceinline__ u64 pk2(float lo, float hi) {
    u64 r; asm("mov.b64 %0, {%1,%2};" : "=l"(r) : "f"(lo), "f"(hi)); return r;
}
__device__ __forceinline__ void upk2(u64 v, float& lo, float& hi) {
    asm("mov.b64 {%0,%1}, %2;" : "=f"(lo), "=f"(hi) : "l"(v));
}
__device__ __forceinline__ u64 ffma2(u64 a, u64 b, u64 c) {
    u64 d; asm("fma.rn.f32x2 %0, %1, %2, %3;" : "=l"(d) : "l"(a), "l"(b), "l"(c)); return d;
}

// ---------------- scratch ----------------
__device__ float g_feats[NP * 32];
__device__ float g_dfp[NP * 96];
__device__ float g_W1T[256 * 256];
__device__ float g_W0T[256 * 35];

// ---------------- weight transpose ----------------
__global__ void k_transpose(const float* __restrict__ W0, const float* __restrict__ W1) {
    int total = 256 * 256 + 256 * 35;
    for (int g = blockIdx.x * blockDim.x + threadIdx.x; g < total; g += gridDim.x * blockDim.x) {
        if (g < 65536) {
            int j = g >> 8, i = g & 255;
            g_W1T[j * 256 + i] = W1[i * 256 + j];
        } else {
            int t = g - 65536;
            int j = t / 35, i = t - j * 35;
            g_W0T[t] = W0[i * 256 + j];
        }
    }
}

// ---------------- trilinear sampling: feats + d feat/d p ----------------
__global__ void k_sample(const float* __restrict__ pts,
                         const float* __restrict__ vol0,
                         const float* __restrict__ vol1) {
    extern __shared__ float sm[];
    float* sFeat = sm;            // 64*33
    float* sDfp  = sm + 2112;     // 64*97
    int tid = threadIdx.x;
    int p = blockIdx.x * 64 + tid;

    float px = pts[p * 3 + 0], py = pts[p * 3 + 1], pz = pts[p * 3 + 2];
    float x = px * 95.f, y = py * 95.f, z = pz * 95.f;
    int x0 = (int)floorf(x); x0 = min(max(x0, 0), 94);
    int y0 = (int)floorf(y); y0 = min(max(y0, 0), 94);
    int z0 = (int)floorf(z); z0 = min(max(z0, 0), 94);
    float xd = x - (float)x0, yd = y - (float)y0, zd = z - (float)z0;
    float wx0 = 1.f - xd, wx1 = xd;
    float wy0 = 1.f - yd, wy1 = yd;
    float wz0 = 1.f - zd, wz1 = zd;

    int base = (z0 * 96 + y0) * 96 + x0;
    const float* vols[2] = { vol0, vol1 };

    #pragma unroll
    for (int v = 0; v < 2; v++) {
        const float* vb = vols[v] + base;
        #pragma unroll 4
        for (int c = 0; c < 16; c++) {
            const float* q = vb + c * GD3;
            float v000 = __ldg(q);        float v001 = __ldg(q + 1);
            float v010 = __ldg(q + 96);   float v011 = __ldg(q + 97);
            float v100 = __ldg(q + 9216); float v101 = __ldg(q + 9217);
            float v110 = __ldg(q + 9312); float v111 = __ldg(q + 9313);
            float feat = wz0 * (wy0 * (v000 * wx0 + v001 * wx1) + wy1 * (v010 * wx0 + v011 * wx1))
                       + wz1 * (wy0 * (v100 * wx0 + v101 * wx1) + wy1 * (v110 * wx0 + v111 * wx1));
            float dfx = 95.f * (wz0 * (wy0 * (v001 - v000) + wy1 * (v011 - v010))
                              + wz1 * (wy0 * (v101 - v100) + wy1 * (v111 - v110)));
            float dfy = 95.f * (wz0 * (wx0 * (v010 - v000) + wx1 * (v011 - v001))
                              + wz1 * (wx0 * (v110 - v100) + wx1 * (v111 - v101)));
            float dfz = 95.f * (wy0 * (wx0 * (v100 - v000) + wx1 * (v101 - v001))
                              + wy1 * (wx0 * (v110 - v010) + wx1 * (v111 - v011)));
            int fi = (c >> 3) * 16 + v * 8 + (c & 7);
            sFeat[tid * 33 + fi] = feat;
            sDfp[tid * 97 + fi]      = dfx;
            sDfp[tid * 97 + 32 + fi] = dfy;
            sDfp[tid * 97 + 64 + fi] = dfz;
        }
    }
    __syncthreads();
    int fb = blockIdx.x * 64 * 32;
    for (int t = tid; t < 2048; t += 64)
        g_feats[fb + t] = sFeat[(t >> 5) * 33 + (t & 31)];
    int db = blockIdx.x * 64 * 96;
    for (int t = tid; t < 6144; t += 64) {
        int pp = t / 96, q = t - pp * 96;
        g_dfp[db + t] = sDfp[pp * 97 + q];
    }
}

// ---------------- 64pt x 256col GEMM (R8-proven mapping, CH=16 chunks) ----------------
// lane owns cols [4*lane..+3] and [128+4*lane..+3]; weight LDS.128 coalesced.
// maskBits: optional 64x256 bitmask (relu' of a previous layer).
// sOut may alias sA (pre-epilogue barrier).
__device__ __forceinline__ void gemm64(
    const float* sA, int lda, const float* __restrict__ gW, int KD,
    const float* __restrict__ gBias, float* sOut, float* sW,
    bool do_relu, const unsigned* maskBits)
{
    int tid = threadIdx.x;
    int p0 = (tid >> 5) * 8;
    int lane = tid & 31;
    int j0a = 4 * lane;
    int j0b = 128 + 4 * lane;
    u64 acc[8][4];
    u64 binit[4];
    if (gBias) {
        binit[0] = *(const u64*)(gBias + j0a);
        binit[1] = *(const u64*)(gBias + j0a + 2);
        binit[2] = *(const u64*)(gBias + j0b);
        binit[3] = *(const u64*)(gBias + j0b + 2);
    } else {
        binit[0] = binit[1] = binit[2] = binit[3] = 0ull;
    }
    #pragma unroll
    for (int i = 0; i < 8; i++)
        #pragma unroll
        for (int jp = 0; jp < 4; jp++) acc[i][jp] = binit[jp];

    for (int k0 = 0; k0 < KD; k0 += 16) {
        int kc = KD - k0; if (kc > 16) kc = 16;
        __syncthreads();
        for (int t = tid; t < kc * 64; t += 256) {
            int r = t >> 6, c = t & 63;
            ((float4*)sW)[r * 64 + c] = ((const float4*)(gW + (size_t)(k0 + r) * 256))[c];
        }
        __syncthreads();
        int kk = 0;
        for (; kk + 1 < kc; kk += 2) {
            u64 ap[8];
            #pragma unroll
            for (int i = 0; i < 8; i++)
                ap[i] = *(const u64*)(sA + (p0 + i) * lda + k0 + kk);
            float4 wA0 = *(const float4*)(sW + kk * 256 + j0a);
            float4 wB0 = *(const float4*)(sW + kk * 256 + j0b);
            float4 wA1 = *(const float4*)(sW + (kk + 1) * 256 + j0a);
            float4 wB1 = *(const float4*)(sW + (kk + 1) * 256 + j0b);
            u64 w0[4] = { pk2(wA0.x, wA0.y), pk2(wA0.z, wA0.w),
                          pk2(wB0.x, wB0.y), pk2(wB0.z, wB0.w) };
            u64 w1[4] = { pk2(wA1.x, wA1.y), pk2(wA1.z, wA1.w),
                          pk2(wB1.x, wB1.y), pk2(wB1.z, wB1.w) };
            #pragma unroll
            for (int i = 0; i < 8; i++) {
                float alo, ahi; upk2(ap[i], alo, ahi);
                u64 a0 = pk2(alo, alo), a1 = pk2(ahi, ahi);
                #pragma unroll
                for (int jp = 0; jp < 4; jp++)
                    acc[i][jp] = ffma2(a0, w0[jp], acc[i][jp]);
                #pragma unroll
                for (int jp = 0; jp < 4; jp++)
                    acc[i][jp] = ffma2(a1, w1[jp], acc[i][jp]);
            }
        }
        if (kc & 1) {
            int k = kc - 1;
            float4 wA = *(const float4*)(sW + k * 256 + j0a);
            float4 wB = *(const float4*)(sW + k * 256 + j0b);
            u64 w2[4] = { pk2(wA.x, wA.y), pk2(wA.z, wA.w),
                          pk2(wB.x, wB.y), pk2(wB.z, wB.w) };
            #pragma unroll
            for (int i = 0; i < 8; i++) {
                float av = sA[(p0 + i) * lda + k0 + k];
                u64 a2 = pk2(av, av);
                #pragma unroll
                for (int jp = 0; jp < 4; jp++)
                    acc[i][jp] = ffma2(a2, w2[jp], acc[i][jp]);
            }
        }
    }
    __syncthreads();   // allow sOut == sA
    #pragma unroll
    for (int i = 0; i < 8; i++) {
        float vv[8];
        upk2(acc[i][0], vv[0], vv[1]);
        upk2(acc[i][1], vv[2], vv[3]);
        upk2(acc[i][2], vv[4], vv[5]);
        upk2(acc[i][3], vv[6], vv[7]);
        if (do_relu) {
            #pragma unroll
            for (int j = 0; j < 8; j++) vv[j] = fmaxf(vv[j], 0.f);
        }
        if (maskBits) {
            unsigned wa = maskBits[(p0 + i) * 8 + (j0a >> 5)];
            unsigned wb = maskBits[(p0 + i) * 8 + (j0b >> 5)];
            int ba = j0a & 31, bb = j0b & 31;
            #pragma unroll
            for (int j = 0; j < 4; j++) {
                vv[j]     = (wa >> (ba + j)) & 1u ? vv[j]     : 0.f;
                vv[4 + j] = (wb >> (bb + j)) & 1u ? vv[4 + j] : 0.f;
            }
        }
        *(float4*)(sOut + (p0 + i) * 256 + j0a) = make_float4(vv[0], vv[1], vv[2], vv[3]);
        *(float4*)(sOut + (p0 + i) * 256 + j0b) = make_float4(vv[4], vv[5], vv[6], vv[7]);
    }
    __syncthreads();
}

// ---------------- fused MLP: forward + backward + rgb + elementwise ----------------
// smem floats: sW 4096 | sH 16384 | sX 3584 (Gx aliased) | sMask 512 |
//              sGeo 960 | sGrad 192 | sSdf 64 | sB 256   = 26048 (104.2KB)
__global__ __launch_bounds__(256, 2) void k_fused(
    const float* __restrict__ pts, const float* __restrict__ dirs,
    const float* __restrict__ deltas,
    const float* __restrict__ W0, const float* __restrict__ b0,
    const float* __restrict__ W1, const float* __restrict__ b1,
    const float* __restrict__ W2, const float* __restrict__ b2,
    const float* __restrict__ Wr0, const float* __restrict__ br0,
    const float* __restrict__ Wr1, const float* __restrict__ br1,
    const float* __restrict__ beta, const float* __restrict__ variance,
    float* __restrict__ out)
{
    extern __shared__ float sm[];
    float* sW    = sm;                 // 4096
    float* sH    = sm + 4096;          // 16384 (H1 -> H2 -> G2/G1 -> Hr)
    float* sX    = sm + 20480;         // 3584 (X36, then Gx 2240, then X56)
    unsigned* sMask = (unsigned*)(sm + 24064);  // 512 words
    float* sGeo  = sm + 24576;         // 960
    float* sGrad = sm + 25536;         // 192
    float* sSdf  = sm + 25728;         // 64
    float* sB    = sm + 25792;         // 256
    int tid = threadIdx.x;
    int pb = blockIdx.x * 64;

    // ---- stage L0 input X = [pts | feats] (lda 36) ----
    for (int t = tid; t < 192; t += 256) { int p = t / 3, a = t - p * 3; sX[p * 36 + a] = pts[(pb + p) * 3 + a]; }
    for (int t = tid; t < 2048; t += 256) { int p = t >> 5, c = t & 31; sX[p * 36 + 3 + c] = g_feats[pb * 32 + t]; }
    sB[tid] = W2[tid * 16];            // W2 column 0 (for G2 later)
    __syncthreads();

    // ---- L0: X @ W0 + b0, relu -> H1 in sH ----
    gemm64(sX, 36, W0, 35, b0, sH, sW, true, nullptr);

    // ---- H1>0 bitmask ----
    for (int t = tid; t < 512; t += 256) {
        int p = t >> 3, w = t & 7;
        const float* h = sH + p * 256 + w * 32;
        unsigned m = 0;
        #pragma unroll 8
        for (int i = 0; i < 32; i++) m |= (h[i] > 0.f) ? (1u << i) : 0u;
        sMask[t] = m;
    }
    __syncthreads();

    // ---- L1: H1 @ W1 + b1, relu -> H2 in place ----
    gemm64(sH, 256, W1, 256, b1, sH, sW, true, nullptr);

    // ---- L2 head: 256 -> 16 (sdf + geo); W2 fits sW exactly (4096) ----
    for (int t = tid; t < 1024; t += 256) ((float4*)sW)[t] = ((const float4*)W2)[t];
    __syncthreads();
    {
        int jc = tid & 15, pr = tid >> 4;
        u64 acc2[4];
        float bb = b2[jc];
        #pragma unroll
        for (int i = 0; i < 4; i++) acc2[i] = pk2(bb, 0.f);
        for (int k = 0; k < 256; k += 2) {
            u64 w2 = pk2(sW[k * 16 + jc], sW[k * 16 + 16 + jc]);
            #pragma unroll
            for (int i = 0; i < 4; i++)
                acc2[i] = ffma2(*(const u64*)(sH + (pr * 4 + i) * 256 + k), w2, acc2[i]);
        }
        #pragma unroll
        for (int i = 0; i < 4; i++) {
            float lo, hi; upk2(acc2[i], lo, hi);
            float a = lo + hi;
            int p = pr * 4 + i;
            if (jc == 0) { sSdf[p] = a; out[(size_t)NP * 4 + pb + p] = a; }
            else         sGeo[p * 15 + jc - 1] = a;
        }
    }
    __syncthreads();

    // ---- G2 = (H2>0) ? W2col0 : 0, in place over sH ----
    for (int t = tid; t < 4096; t += 256) {
        float4 h = ((const float4*)sH)[t];
        int j = (t & 63) * 4;
        float4 g;
        g.x = h.x > 0.f ? sB[j]     : 0.f;
        g.y = h.y > 0.f ? sB[j + 1] : 0.f;
        g.z = h.z > 0.f ? sB[j + 2] : 0.f;
        g.w = h.w > 0.f ? sB[j + 3] : 0.f;
        ((float4*)sH)[t] = g;
    }
    // ---- G1 = (G2 @ W1^T) * (H1>0 bits), in place ----
    gemm64(sH, 256, g_W1T, 256, nullptr, sH, sW, false, sMask);

    // ---- Gx = G1 @ W0^T (N=35), W0T in 4 chunks of 64 k-rows; Gx -> sX ----
    float* sGx = sX;                   // X36 dead; 2240 <= 3584
    #pragma unroll
    for (int ch = 0; ch < 4; ch++) {
        __syncthreads();
        for (int t = tid; t < 2240; t += 256) sW[t] = g_W0T[ch * 2240 + t];
        __syncthreads();
        for (int o = tid; o < 2240; o += 256) {
            int p = o / 35, i = o - p * 35;
            u64 a2 = 0ull;
            const float* gr = sH + p * 256 + ch * 64;
            for (int k = 0; k < 64; k += 2)
                a2 = ffma2(*(const u64*)(gr + k), pk2(sW[k * 35 + i], sW[k * 35 + 35 + i]), a2);
            float lo, hi; upk2(a2, lo, hi);
            float a = lo + hi;
            if (ch) a += sGx[o];
            sGx[o] = a;
        }
    }
    __syncthreads();

    // ---- gradients + normals ----
    if (tid < 64) {
        int p = tid, pt = pb + p;
        const float* dfp = g_dfp + (size_t)pt * 96;
        float gx = sGx[p * 35], gy = sGx[p * 35 + 1], gz = sGx[p * 35 + 2];
        #pragma unroll
        for (int c = 0; c < 32; c++) {
            float q = sGx[p * 35 + 3 + c];
            gx = fmaf(q, __ldg(dfp + c),      gx);
            gy = fmaf(q, __ldg(dfp + 32 + c), gy);
            gz = fmaf(q, __ldg(dfp + 64 + c), gz);
        }
        sGrad[p * 3 + 0] = gx; sGrad[p * 3 + 1] = gy; sGrad[p * 3 + 2] = gz;
        out[(size_t)NP * 5 + pt * 3 + 0] = gx;
        out[(size_t)NP * 5 + pt * 3 + 1] = gy;
        out[(size_t)NP * 5 + pt * 3 + 2] = gz;
        float n = sqrtf(gx * gx + gy * gy + gz * gz);
        float inv = 1.f / fmaxf(n, 1e-12f);
        out[(size_t)NP * 8 + pt * 3 + 0] = gx * inv;
        out[(size_t)NP * 8 + pt * 3 + 1] = gy * inv;
        out[(size_t)NP * 8 + pt * 3 + 2] = gz * inv;
    }
    __syncthreads();

    // ---- stage RGB input X56 = [pts | grad | feats | geo | dirs] ----
    for (int t = tid; t < 192; t += 256) {
        int p = t / 3, a = t - p * 3;
        sX[p * 56 + a]      = pts[(pb + p) * 3 + a];
        sX[p * 56 + 3 + a]  = sGrad[t];
        sX[p * 56 + 53 + a] = dirs[(pb + p) * 3 + a];
    }
    __syncthreads();   // sGx (aliased) fully consumed before overwrite of cols 6..52
    for (int t = tid; t < 2048; t += 256) { int p = t >> 5, c = t & 31; sX[p * 56 + 6 + c] = g_feats[pb * 32 + t]; }
    for (int t = tid; t < 960; t += 256) { int p = t / 15, j = t - p * 15; sX[p * 56 + 38 + j] = sGeo[t]; }
    __syncthreads();

    // ---- RGB layer 0: X56 @ Wr0 + br0, relu -> Hr in sH ----
    gemm64(sX, 56, Wr0, 56, br0, sH, sW, true, nullptr);

    // ---- RGB head: 256 -> 3, sigmoid ----
    for (int t = tid; t < 768; t += 256) sW[t] = Wr1[t];
    __syncthreads();
    for (int o = tid; o < 192; o += 256) {
        int p = o / 3, c = o - p * 3;
        u64 a2 = pk2(br1[c], 0.f);
        const float* hr = sH + p * 256;
        for (int k = 0; k < 256; k += 2)
            a2 = ffma2(*(const u64*)(hr + k), pk2(sW[k * 3 + c], sW[k * 3 + 3 + c]), a2);
        float lo, hi; upk2(a2, lo, hi);
        out[(size_t)(pb + p) * 3 + c] = 1.f / (1.f + expf(-(lo + hi)));
    }

    // ---- density + alpha ----
    if (tid < 64) {
        int pt = pb + tid;
        float sdf = sSdf[tid];
        float d   = deltas[pt];
        float gx = sGrad[tid * 3], gy = sGrad[tid * 3 + 1], gz = sGrad[tid * 3 + 2];
        float dx = dirs[pt * 3], dy = dirs[pt * 3 + 1], dz = dirs[pt * 3 + 2];
        float be = fabsf(beta[0]) + 1e-4f;
        float sg = (sdf > 0.f) ? 1.f : ((sdf < 0.f) ? -1.f : 0.f);
        float density = (0.5f + 0.5f * sg * expm1f(-fabsf(sdf) / be)) / be;
        float iv = expf(variance[0] * 10.f);
        iv = fminf(fmaxf(iv, 1e-6f), 1e6f);
        float tc = dx * gx + dy * gy + dz * gz;
        float ic = -fmaxf(-tc, 0.f);                 // COS_ANNEAL = 1
        float en = sdf + ic * d * 0.5f;
        float ep = sdf - ic * d * 0.5f;
        float pc = 1.f / (1.f + expf(-ep * iv));
        float nc = 1.f / (1.f + expf(-en * iv));
        float al = (pc - nc + 1e-5f) / (pc + 1e-5f);
        al = fminf(fmaxf(al, 0.f), 1.f);
        out[(size_t)NP * 3 + pt]  = density;
        out[(size_t)NP * 11 + pt] = al;
    }
}

// ---------------- launch ----------------
extern "C" void kernel_launch(void* const* d_in, const int* in_sizes, int n_in,
                              void* d_out, int out_size) {
    const float* points     = (const float*)d_in[0];
    const float* directions = (const float*)d_in[1];
    const float* deltas     = (const float*)d_in[2];
    const float* vol0       = (const float*)d_in[3];
    const float* vol1       = (const float*)d_in[4];
    const float* W0  = (const float*)d_in[5];
    const float* b0  = (const float*)d_in[6];
    const float* W1  = (const float*)d_in[7];
    const float* b1  = (const float*)d_in[8];
    const float* W2  = (const float*)d_in[9];
    const float* b2  = (const float*)d_in[10];
    const float* Wr0 = (const float*)d_in[11];
    const float* br0 = (const float*)d_in[12];
    const float* Wr1 = (const float*)d_in[13];
    const float* br1 = (const float*)d_in[14];
    const float* beta     = (const float*)d_in[15];
    const float* variance = (const float*)d_in[16];
    float* out = (float*)d_out;

    cudaFuncSetAttribute(k_fused, cudaFuncAttributeMaxDynamicSharedMemorySize, 26048 * 4);

    k_transpose<<<128, 256>>>(W0, W1);
    k_sample<<<NP / 64, 64, 8320 * 4>>>(points, vol0, vol1);
    k_fused<<<NP / 64, 256, 26048 * 4>>>(points, directions, deltas,
                                         W0, b0, W1, b1, W2, b2,
                                         Wr0, br0, Wr1, br1, beta, variance, out);
}